// round 11
// baseline (speedup 1.0000x reference)
#include <cuda_runtime.h>

#define NB    500            // DVH points per batch
#define NH    501            // histogram buckets (searchsorted index 0..500)
#define BATCH 4
#define NPER  (128*128*128)  // 2,097,152 elements per batch
#define NVEC  (NPER/4)       // float4 count per batch = 524288
#define GX    256            // x-blocks per batch
#define TPB   256
#define NCTAS (GX * BATCH)   // 1024
#define ITERS (NVEC / (GX * TPB))   // 8, exact

// Persistent scratch (zero-init at module load; the last CTA re-zeroes after
// use, so every graph replay sees clean state).
__device__ int g_hist[BATCH][NH];   // difference histogram: pred - gt
__device__ int g_mcount[BATCH];     // masked-voxel count per batch
__device__ unsigned int g_ticket;   // completed-CTA counter

// ---------------------------------------------------------------------------
// Epilogue, isolated in a __noinline__ function so its codegen cannot perturb
// the histogram mainloop (the R4/R5 fused versions lost ~10us there).
// Executed by all 256 threads of the LAST CTA only. No membar anywhere.
// ---------------------------------------------------------------------------
__device__ __noinline__ void finalize(float* __restrict__ out)
{
    __shared__ float warp_acc[4];
    const int tid  = threadIdx.x;
    const int wid  = tid >> 5;
    const int lane = tid & 31;
    const unsigned FULL = 0xffffffffu;

    if (wid < BATCH) {
        const int b = wid;                     // one warp per batch
        const float denom = (float)__ldcg(&g_mcount[b]) + 1e-6f;

        // 16 chunks of 32: register-resident inclusive suffix scan per chunk
        float s[16];
        #pragma unroll
        for (int k = 0; k < 16; k++) {
            int idx = k * 32 + lane;
            float v = (idx < NH) ? (float)__ldcg(&g_hist[b][idx]) : 0.0f;
            #pragma unroll
            for (int off = 1; off < 32; off <<= 1) {
                float t = __shfl_down_sync(FULL, v, off);
                if (lane + off < 32) v += t;
            }
            s[k] = v;
        }
        // chunk tails (suffix of chunk totals = lane-0 values)
        float tails[16];
        float run = 0.0f;
        #pragma unroll
        for (int k = 15; k >= 0; k--) {
            tails[k] = run;
            run += __shfl_sync(FULL, s[k], 0);
        }
        // loss over DVH points: suffix at histogram index 1..500
        float acc = 0.0f;
        #pragma unroll
        for (int k = 0; k < 16; k++) {
            int idx = k * 32 + lane;
            if (idx >= 1 && idx <= NB) {
                float d = (s[k] + tails[k]) / denom;
                acc += d * d;
            }
        }
        #pragma unroll
        for (int off = 16; off > 0; off >>= 1)
            acc += __shfl_down_sync(FULL, acc, off);
        if (lane == 0) warp_acc[b] = acc;
    }
    __syncthreads();
    if (tid == 0)
        out[0] = (warp_acc[0] + warp_acc[1] + warp_acc[2] + warp_acc[3])
               / (float)(BATCH * NB);

    // self-clean for the next graph replay
    for (int i = tid; i < BATCH * NH; i += TPB) ((int*)g_hist)[i] = 0;
    if (tid < BATCH) g_mcount[tid] = 0;
    if (tid == 0)    g_ticket = 0u;
}

__global__ __launch_bounds__(TPB, 6) void hist_k(
    const float* __restrict__ dpred,
    const float* __restrict__ dgt,
    const float* __restrict__ msk,
    float* __restrict__ out)
{
    __shared__ int sh[NH];
    __shared__ bool is_last;
    const int tid = threadIdx.x;
    for (int i = tid; i < NH; i += TPB) sh[i] = 0;
    __syncthreads();

    const int b = blockIdx.y;
    const float4* __restrict__ p4 = (const float4*)(dpred + (size_t)b * NPER);
    const float4* __restrict__ g4 = (const float4*)(dgt   + (size_t)b * NPER);
    const float4* __restrict__ m4 = (const float4*)(msk   + (size_t)b * NPER);

    const float INVH = 499.0f / 75.0f;   // 1/h for bins = linspace(0,75,500)
    const int base = blockIdx.x * TPB + tid;
    int mc = 0;

    #pragma unroll 2
    for (int j = 0; j < ITERS; j++) {
        const int i = base + j * (GX * TPB);
        float4 m = __ldcs(&m4[i]);           // streaming: read-once data
        float4 a = __ldcs(&p4[i]);
        float4 g = __ldcs(&g4[i]);
        float mm[4] = {m.x, m.y, m.z, m.w};
        float aa[4] = {a.x, a.y, a.z, a.w};
        float gg[4] = {g.x, g.y, g.z, g.w};
        #pragma unroll
        for (int e = 0; e < 4; e++) {
            if (mm[e] != 0.0f) {               // mask is exactly 0.0 or 1.0
                mc++;
                int cp = min((int)(aa[e] * INVH) + 1, NB);
                int cg = min((int)(gg[e] * INVH) + 1, NB);
                atomicAdd(&sh[cp],  1);        // diff histogram: +pred
                atomicAdd(&sh[cg], -1);        //                 -gt
            }
        }
    }

    // masked count: warp reduce, one global RED per warp
    #pragma unroll
    for (int off = 16; off > 0; off >>= 1)
        mc += __shfl_down_sync(0xffffffffu, mc, off);
    if ((tid & 31) == 0 && mc) atomicAdd(&g_mcount[b], mc);

    __syncthreads();
    for (int i = tid; i < NH; i += TPB) {
        int v = sh[i];
        if (v) atomicAdd(&g_hist[b][i], v);    // RED, fire-and-forget
    }

    // ---- last-CTA handoff: NO membar. bar.sync gives CTA-scope ordering of
    // all threads' REDs before tid0; the acq_rel gpu-scope atomic publishes
    // them (release) and, for the winner, acquires all other CTAs' work.
    __syncthreads();
    if (tid == 0) {
        unsigned t;
        asm volatile("atom.acq_rel.gpu.add.u32 %0, [%1], %2;"
                     : "=r"(t) : "l"(&g_ticket), "r"(1u) : "memory");
        is_last = (t == NCTAS - 1);
    }
    __syncthreads();
    if (is_last) finalize(out);
}

extern "C" void kernel_launch(void* const* d_in, const int* in_sizes, int n_in,
                              void* d_out, int out_size)
{
    const float* dpred = (const float*)d_in[0];
    const float* dgt   = (const float*)d_in[1];
    const float* msk   = (const float*)d_in[2];

    dim3 grid(GX, BATCH);            // 1024 CTAs, ~6/SM, single wave
    hist_k<<<grid, TPB>>>(dpred, dgt, msk, (float*)d_out);
}

// round 12
// speedup vs baseline: 1.5360x; 1.5360x over previous
#include <cuda_runtime.h>

#define NB    500            // DVH points per batch
#define NH    501            // histogram buckets (searchsorted index 0..500)
#define BATCH 4
#define NPER  (128*128*128)  // 2,097,152 elements per batch
#define NVEC  (NPER/4)       // float4 count per batch = 524288
#define GX    256            // x-blocks per batch
#define TPB   256
#define ITERS (NVEC / (GX * TPB))   // 8, exact

// Persistent scratch (zero-init at module load; fin_k re-zeroes after use,
// so every graph replay sees clean state).
__device__ int g_hist[BATCH][NH];   // difference histogram: pred - gt
__device__ int g_mcount[BATCH];     // masked-voxel count per batch

__global__ __launch_bounds__(TPB, 6) void hist_k(
    const float* __restrict__ dpred,
    const float* __restrict__ dgt,
    const float* __restrict__ msk)
{
    __shared__ int sh[NH];
    const int tid = threadIdx.x;
    for (int i = tid; i < NH; i += TPB) sh[i] = 0;
    __syncthreads();

    const int b = blockIdx.y;
    const float4* __restrict__ p4 = (const float4*)(dpred + (size_t)b * NPER);
    const float4* __restrict__ g4 = (const float4*)(dgt   + (size_t)b * NPER);
    const float4* __restrict__ m4 = (const float4*)(msk   + (size_t)b * NPER);

    const float INVH = 499.0f / 75.0f;   // 1/h for bins = linspace(0,75,500)
    const int base = blockIdx.x * TPB + tid;
    int mc = 0;

    #pragma unroll 2
    for (int j = 0; j < ITERS; j++) {
        const int i = base + j * (GX * TPB);
        float4 m = __ldcs(&m4[i]);           // streaming: read-once data
        float4 a = __ldcs(&p4[i]);
        float4 g = __ldcs(&g4[i]);
        float mm[4] = {m.x, m.y, m.z, m.w};
        float aa[4] = {a.x, a.y, a.z, a.w};
        float gg[4] = {g.x, g.y, g.z, g.w};
        #pragma unroll
        for (int e = 0; e < 4; e++) {
            if (mm[e] != 0.0f) {               // mask is exactly 0.0 or 1.0
                mc++;
                int cp = min((int)(aa[e] * INVH) + 1, NB);
                int cg = min((int)(gg[e] * INVH) + 1, NB);
                atomicAdd(&sh[cp],  1);        // diff histogram: +pred
                atomicAdd(&sh[cg], -1);        //                 -gt
            }
        }
    }

    // masked count: warp reduce, one global RED per warp
    #pragma unroll
    for (int off = 16; off > 0; off >>= 1)
        mc += __shfl_down_sync(0xffffffffu, mc, off);
    if ((tid & 31) == 0 && mc) atomicAdd(&g_mcount[b], mc);

    __syncthreads();
    for (int i = tid; i < NH; i += TPB) {
        int v = sh[i];
        if (v) atomicAdd(&g_hist[b][i], v);    // RED, fire-and-forget
    }

    // PDL: let the dependent fin_k begin its launch/ramp while remaining
    // hist CTAs drain. Memory visibility for fin comes from its
    // cudaGridDependencySynchronize(), not from this trigger.
#if __CUDA_ARCH__ >= 900
    cudaTriggerProgrammaticLaunchCompletion();
#endif
}

// One warp per batch; register-resident suffix scan; re-zeroes scratch.
__global__ __launch_bounds__(128) void fin_k(float* __restrict__ out) {
    __shared__ float warp_acc[4];
    const int tid  = threadIdx.x;
    const int wid  = tid >> 5;
    const int lane = tid & 31;
    const unsigned FULL = 0xffffffffu;

#if __CUDA_ARCH__ >= 900
    cudaGridDependencySynchronize();   // wait for hist grid + visibility
#endif

    if (wid < BATCH) {
        const int b = wid;
        const float denom = (float)g_mcount[b] + 1e-6f;

        // 16 chunks of 32: register-resident inclusive suffix scan per chunk
        float s[16];
        #pragma unroll
        for (int k = 0; k < 16; k++) {
            int idx = k * 32 + lane;
            float v = (idx < NH) ? (float)g_hist[b][idx] : 0.0f;
            #pragma unroll
            for (int off = 1; off < 32; off <<= 1) {
                float t = __shfl_down_sync(FULL, v, off);
                if (lane + off < 32) v += t;
            }
            s[k] = v;
        }
        // chunk tails (suffix of chunk totals = lane-0 values)
        float tails[16];
        float run = 0.0f;
        #pragma unroll
        for (int k = 15; k >= 0; k--) {
            tails[k] = run;
            run += __shfl_sync(FULL, s[k], 0);
        }
        // loss over DVH points: suffix at histogram index 1..500
        float acc = 0.0f;
        #pragma unroll
        for (int k = 0; k < 16; k++) {
            int idx = k * 32 + lane;
            if (idx >= 1 && idx <= NB) {
                float d = (s[k] + tails[k]) / denom;
                acc += d * d;
            }
        }
        #pragma unroll
        for (int off = 16; off > 0; off >>= 1)
            acc += __shfl_down_sync(FULL, acc, off);
        if (lane == 0) warp_acc[b] = acc;
    }
    __syncthreads();
    if (tid == 0)
        out[0] = (warp_acc[0] + warp_acc[1] + warp_acc[2] + warp_acc[3])
               / (float)(BATCH * NB);

    // self-clean for next replay (graph-capture safe, no extra kernel)
    for (int i = tid; i < BATCH * NH; i += 128) ((int*)g_hist)[i] = 0;
    if (tid < BATCH) g_mcount[tid] = 0;
}

extern "C" void kernel_launch(void* const* d_in, const int* in_sizes, int n_in,
                              void* d_out, int out_size)
{
    const float* dpred = (const float*)d_in[0];
    const float* dgt   = (const float*)d_in[1];
    const float* msk   = (const float*)d_in[2];

    dim3 grid(GX, BATCH);            // 1024 CTAs, ~6/SM, single wave
    hist_k<<<grid, TPB>>>(dpred, dgt, msk);

    // fin_k launched with Programmatic Stream Serialization: its launch/ramp
    // overlaps hist_k's tail; cudaGridDependencySynchronize() inside fin_k
    // enforces the data dependency.
    cudaLaunchConfig_t cfg = {};
    cfg.gridDim  = dim3(1, 1, 1);
    cfg.blockDim = dim3(128, 1, 1);
    cfg.dynamicSmemBytes = 0;
    cfg.stream = 0;
    cudaLaunchAttribute attr[1];
    attr[0].id = cudaLaunchAttributeProgrammaticStreamSerialization;
    attr[0].val.programmaticStreamSerializationAllowed = 1;
    cfg.attrs = attr;
    cfg.numAttrs = 1;
    float* out = (float*)d_out;
    cudaError_t e = cudaLaunchKernelEx(&cfg, fin_k, out);
    if (e != cudaSuccess) {
        // Fallback: plain dependent launch (still correct).
        fin_k<<<1, 128>>>(out);
    }
}

// round 13
// speedup vs baseline: 1.8395x; 1.1976x over previous
#include <cuda_runtime.h>

#define NB    500            // DVH points per batch
#define NH    501            // histogram buckets (searchsorted index 0..500)
#define BATCH 4
#define NPER  (128*128*128)  // 2,097,152 elements per batch
#define NVEC  (NPER/4)       // float4 count per batch = 524288
#define GX    222            // x-blocks per batch -> 888 CTAs = 148 SMs x 6 (ONE wave)
#define TPB   256

// Persistent scratch (zero-init at module load; fin_k re-zeroes after use,
// so every graph replay sees clean state).
__device__ int g_hist[BATCH][NH];   // difference histogram: pred - gt
__device__ int g_mcount[BATCH];     // masked-voxel count per batch

__global__ __launch_bounds__(TPB, 6) void hist_k(
    const float* __restrict__ dpred,
    const float* __restrict__ dgt,
    const float* __restrict__ msk)
{
    __shared__ int sh[NH];
    const int tid = threadIdx.x;
    for (int i = tid; i < NH; i += TPB) sh[i] = 0;
    __syncthreads();

    const int b = blockIdx.y;
    const float4* __restrict__ p4 = (const float4*)(dpred + (size_t)b * NPER);
    const float4* __restrict__ g4 = (const float4*)(dgt   + (size_t)b * NPER);
    const float4* __restrict__ m4 = (const float4*)(msk   + (size_t)b * NPER);

    const float INVH = 499.0f / 75.0f;   // 1/h for bins = linspace(0,75,500)
    const int stride = GX * TPB;         // 56832
    int mc = 0;

    #pragma unroll 2
    for (int i = blockIdx.x * TPB + tid; i < NVEC; i += stride) {
        float4 m = __ldcs(&m4[i]);           // streaming: read-once data
        float4 a = __ldcs(&p4[i]);
        float4 g = __ldcs(&g4[i]);
        float mm[4] = {m.x, m.y, m.z, m.w};
        float aa[4] = {a.x, a.y, a.z, a.w};
        float gg[4] = {g.x, g.y, g.z, g.w};
        #pragma unroll
        for (int e = 0; e < 4; e++) {
            if (mm[e] != 0.0f) {               // mask is exactly 0.0 or 1.0
                mc++;
                int cp = min((int)(aa[e] * INVH) + 1, NB);
                int cg = min((int)(gg[e] * INVH) + 1, NB);
                atomicAdd(&sh[cp],  1);        // diff histogram: +pred
                atomicAdd(&sh[cg], -1);        //                 -gt
            }
        }
    }

    // masked count: warp reduce, one global RED per warp
    #pragma unroll
    for (int off = 16; off > 0; off >>= 1)
        mc += __shfl_down_sync(0xffffffffu, mc, off);
    if ((tid & 31) == 0 && mc) atomicAdd(&g_mcount[b], mc);

    __syncthreads();
    for (int i = tid; i < NH; i += TPB) {
        int v = sh[i];
        if (v) atomicAdd(&g_hist[b][i], v);    // RED, fire-and-forget
    }

    // PDL: let the dependent fin_k begin its launch/ramp while remaining
    // hist CTAs drain. Memory visibility for fin comes from its
    // cudaGridDependencySynchronize(), not from this trigger.
#if __CUDA_ARCH__ >= 900
    cudaTriggerProgrammaticLaunchCompletion();
#endif
}

// One warp per batch; register-resident suffix scan; re-zeroes scratch.
__global__ __launch_bounds__(128) void fin_k(float* __restrict__ out) {
    __shared__ float warp_acc[4];
    const int tid  = threadIdx.x;
    const int wid  = tid >> 5;
    const int lane = tid & 31;
    const unsigned FULL = 0xffffffffu;

#if __CUDA_ARCH__ >= 900
    cudaGridDependencySynchronize();   // wait for hist grid + visibility
#endif

    if (wid < BATCH) {
        const int b = wid;
        const float denom = (float)g_mcount[b] + 1e-6f;

        // 16 chunks of 32: register-resident inclusive suffix scan per chunk
        float s[16];
        #pragma unroll
        for (int k = 0; k < 16; k++) {
            int idx = k * 32 + lane;
            float v = (idx < NH) ? (float)g_hist[b][idx] : 0.0f;
            #pragma unroll
            for (int off = 1; off < 32; off <<= 1) {
                float t = __shfl_down_sync(FULL, v, off);
                if (lane + off < 32) v += t;
            }
            s[k] = v;
        }
        // chunk tails (suffix of chunk totals = lane-0 values)
        float tails[16];
        float run = 0.0f;
        #pragma unroll
        for (int k = 15; k >= 0; k--) {
            tails[k] = run;
            run += __shfl_sync(FULL, s[k], 0);
        }
        // loss over DVH points: suffix at histogram index 1..500
        float acc = 0.0f;
        #pragma unroll
        for (int k = 0; k < 16; k++) {
            int idx = k * 32 + lane;
            if (idx >= 1 && idx <= NB) {
                float d = (s[k] + tails[k]) / denom;
                acc += d * d;
            }
        }
        #pragma unroll
        for (int off = 16; off > 0; off >>= 1)
            acc += __shfl_down_sync(FULL, acc, off);
        if (lane == 0) warp_acc[b] = acc;
    }
    __syncthreads();
    if (tid == 0)
        out[0] = (warp_acc[0] + warp_acc[1] + warp_acc[2] + warp_acc[3])
               / (float)(BATCH * NB);

    // self-clean for next replay (graph-capture safe, no extra kernel)
    for (int i = tid; i < BATCH * NH; i += 128) ((int*)g_hist)[i] = 0;
    if (tid < BATCH) g_mcount[tid] = 0;
}

extern "C" void kernel_launch(void* const* d_in, const int* in_sizes, int n_in,
                              void* d_out, int out_size)
{
    const float* dpred = (const float*)d_in[0];
    const float* dgt   = (const float*)d_in[1];
    const float* msk   = (const float*)d_in[2];

    dim3 grid(GX, BATCH);            // 888 CTAs = exactly one full wave @ 6/SM
    hist_k<<<grid, TPB>>>(dpred, dgt, msk);

    // fin_k with Programmatic Stream Serialization (neutral-cost, kept);
    // cudaGridDependencySynchronize() inside fin_k enforces the dependency.
    cudaLaunchConfig_t cfg = {};
    cfg.gridDim  = dim3(1, 1, 1);
    cfg.blockDim = dim3(128, 1, 1);
    cfg.dynamicSmemBytes = 0;
    cfg.stream = 0;
    cudaLaunchAttribute attr[1];
    attr[0].id = cudaLaunchAttributeProgrammaticStreamSerialization;
    attr[0].val.programmaticStreamSerializationAllowed = 1;
    cfg.attrs = attr;
    cfg.numAttrs = 1;
    float* out = (float*)d_out;
    cudaError_t e = cudaLaunchKernelEx(&cfg, fin_k, out);
    if (e != cudaSuccess) {
        fin_k<<<1, 128>>>(out);   // fallback: plain dependent launch
    }
}